// round 14
// baseline (speedup 1.0000x reference)
#include <cuda_runtime.h>
#include <cuda_bf16.h>
#include <cstdint>

// Problem constants
#define BATCH 2
#define SEQ   2048
#define DIM   1024
#define HEADS 16
#define DK    64
#define CL    256
#define HID   512
#define MROWS (BATCH*SEQ)   // 4096

// ---------------- scratch (device globals; no allocation allowed) ----------------
__device__ float g_h[BATCH * HID];
__device__ float g_c[BATCH * DIM];
__device__ __nv_bfloat16 g_ahi[MROWS * DIM];
__device__ __nv_bfloat16 g_alo[MROWS * DIM];
__device__ __nv_bfloat16 g_whi[DIM * DIM];   // transposed: [N][K]
__device__ __nv_bfloat16 g_wlo[DIM * DIM];
__device__ __nv_bfloat16 g_qhi[MROWS * DIM];
__device__ __nv_bfloat16 g_qlo[MROWS * DIM];
__device__ __nv_bfloat16 g_khi[MROWS * DIM];
__device__ __nv_bfloat16 g_klo[MROWS * DIM];
__device__ __nv_bfloat16 g_vhi[MROWS * DIM];
__device__ __nv_bfloat16 g_vlo[MROWS * DIM];
__device__ __nv_bfloat16 g_xhi[MROWS * DIM];
__device__ __nv_bfloat16 g_xlo[MROWS * DIM];

// ================= PTX helpers (baseline PTX only) =================
__device__ __forceinline__ uint32_t smem_u32(const void* p) {
    uint32_t a;
    asm("{ .reg .u64 t; cvta.to.shared.u64 t, %1; cvt.u32.u64 %0, t; }" : "=r"(a) : "l"(p));
    return a;
}
__device__ __forceinline__ void cp_async16(uint32_t dst, const void* src) {
    asm volatile("cp.async.cg.shared.global [%0], [%1], 16;" :: "r"(dst), "l"(src) : "memory");
}
__device__ __forceinline__ void cp_commit() {
    asm volatile("cp.async.commit_group;" ::: "memory");
}
__device__ __forceinline__ void ldsm_x4(uint32_t* r, uint32_t addr) {
    asm volatile("ldmatrix.sync.aligned.m8n8.x4.shared.b16 {%0,%1,%2,%3}, [%4];"
                 : "=r"(r[0]), "=r"(r[1]), "=r"(r[2]), "=r"(r[3]) : "r"(addr));
}
__device__ __forceinline__ void ldsm_x4_t(uint32_t* r, uint32_t addr) {
    asm volatile("ldmatrix.sync.aligned.m8n8.x4.trans.shared.b16 {%0,%1,%2,%3}, [%4];"
                 : "=r"(r[0]), "=r"(r[1]), "=r"(r[2]), "=r"(r[3]) : "r"(addr));
}
__device__ __forceinline__ void mma_bf16(float* d, const uint32_t* a, uint32_t b0, uint32_t b1) {
    asm volatile(
        "mma.sync.aligned.m16n8k16.row.col.f32.bf16.bf16.f32 "
        "{%0,%1,%2,%3}, {%4,%5,%6,%7}, {%8,%9}, {%0,%1,%2,%3};"
        : "+f"(d[0]), "+f"(d[1]), "+f"(d[2]), "+f"(d[3])
        : "r"(a[0]), "r"(a[1]), "r"(a[2]), "r"(a[3]), "r"(b0), "r"(b1));
}
// pack two fp32 into bf16x2: lo half = first arg
__device__ __forceinline__ uint32_t pack2(float lo, float hi) {
    uint32_t r;
    asm("cvt.rn.bf16x2.f32 %0, %1, %2;" : "=r"(r) : "f"(hi), "f"(lo));
    return r;
}
__device__ __forceinline__ void split1(float v, float& h, float& l) {
    h = __bfloat162float(__float2bfloat16(v));
    l = v - h;
}
__device__ __forceinline__ float ex2(float x) {
    float r; asm("ex2.approx.f32 %0, %1;" : "=f"(r) : "f"(x)); return r;
}

// ---------------- split conversions ----------------
__global__ void split_f32(const float4* __restrict__ x, __nv_bfloat16* __restrict__ hi,
                          __nv_bfloat16* __restrict__ lo, int n4) {
    int i = blockIdx.x * blockDim.x + threadIdx.x;
    if (i >= n4) return;
    float4 v = x[i];
    float h0, h1, h2, h3, l0, l1, l2, l3;
    split1(v.x, h0, l0); split1(v.y, h1, l1);
    split1(v.z, h2, l2); split1(v.w, h3, l3);
    ((uint32_t*)hi)[2 * i]     = pack2(h0, h1);
    ((uint32_t*)hi)[2 * i + 1] = pack2(h2, h3);
    ((uint32_t*)lo)[2 * i]     = pack2(l0, l1);
    ((uint32_t*)lo)[2 * i + 1] = pack2(l2, l3);
}

// W [K,N] -> W^T split: hiT/loT [N][K]
__global__ void split_w_T(const float* __restrict__ W, __nv_bfloat16* __restrict__ hiT,
                          __nv_bfloat16* __restrict__ loT) {
    __shared__ float t[32][33];
    int n0 = blockIdx.x * 32, k0 = blockIdx.y * 32;
    int tx = threadIdx.x, ty = threadIdx.y;   // 32 x 8
    #pragma unroll
    for (int i = ty; i < 32; i += 8) t[i][tx] = W[(size_t)(k0 + i) * DIM + n0 + tx];
    __syncthreads();
    #pragma unroll
    for (int i = ty; i < 32; i += 8) {
        float v = t[tx][i];
        float h, l; split1(v, h, l);
        hiT[(size_t)(n0 + i) * DIM + k0 + tx] = __float2bfloat16(h);
        loT[(size_t)(n0 + i) * DIM + k0 + tx] = __float2bfloat16(l);
    }
}

// ---------------- cond MLP ----------------
__global__ void cond_mlp1(const float* __restrict__ cond, const float* __restrict__ Wc1,
                          const float* __restrict__ bc1, float* __restrict__ h) {
    int b = blockIdx.x;
    int j = threadIdx.x;
    float acc = bc1[j];
    const float* cr = cond + b * CL;
    #pragma unroll 8
    for (int k = 0; k < CL; k++) acc = fmaf(cr[k], Wc1[k * HID + j], acc);
    h[b * HID + j] = acc > 0.f ? acc : 0.f;
}
__global__ void cond_mlp2(const float* __restrict__ h, const float* __restrict__ Wc2,
                          float* __restrict__ c) {
    int b = blockIdx.x;
    int n = threadIdx.x;
    float acc = 0.f;
    const float* hr = h + b * HID;
    #pragma unroll 8
    for (int k = 0; k < HID; k++) acc = fmaf(hr[k], Wc2[k * DIM + n], acc);
    c[b * DIM + n] = acc;
}

// ---------------- mma.sync split-bf16 GEMM (128x64 tile, 2-stage, 2 CTAs/SM) ----------------
#define KC 64
#define NCHUNK (DIM / KC)                // 16
#define TPITCH 144
#define TILE_A (128 * TPITCH)            // 18432
#define TILE_B (64 * TPITCH)             // 9216
#define STAGE_BYTES (2 * TILE_A + 2 * TILE_B)   // 55296
#define GEMM_SMEM (2 * STAGE_BYTES)      // 110592 -> 2 CTAs/SM

__device__ __forceinline__ void load_chunk(uint32_t stg, const __nv_bfloat16* Ahi,
                                           const __nv_bfloat16* Alo, const __nv_bfloat16* BhiT,
                                           const __nv_bfloat16* BloT, int bm, int bn, int k0, int tid) {
    // A tiles: 2 x (128 rows x 8 x 16B) = 2048 ops over 256 threads (8 each)
    #pragma unroll
    for (int i = 0; i < 8; i++) {
        int idx = tid + i * 256;             // 0..2047
        int tile = idx >> 10;                // 0=Ahi, 1=Alo
        int r = (idx >> 3) & 127;
        int c = (idx & 7) << 4;
        const __nv_bfloat16* src = tile ? Alo : Ahi;
        cp_async16(stg + (uint32_t)(tile * TILE_A + r * TPITCH + c),
                   (const char*)(src + (size_t)(bm + r) * DIM + k0) + c);
    }
    // B tiles: 2 x (64 rows x 8 x 16B) = 1024 ops (4 each)
    #pragma unroll
    for (int i = 0; i < 4; i++) {
        int idx = tid + i * 256;             // 0..1023
        int tile = idx >> 9;                 // 0=Bhi, 1=Blo
        int r = (idx >> 3) & 63;
        int c = (idx & 7) << 4;
        const __nv_bfloat16* src = tile ? BloT : BhiT;
        cp_async16(stg + (uint32_t)(2 * TILE_A + tile * TILE_B + r * TPITCH + c),
                   (const char*)(src + (size_t)(bn + r) * DIM + k0) + c);
    }
    cp_commit();
}

// Cf!=null: fp32 output. Else: split-bf16 output to Chi/Clo.
__global__ __launch_bounds__(256, 2)
void gemm_mma(const __nv_bfloat16* __restrict__ Ahi, const __nv_bfloat16* __restrict__ Alo,
              const __nv_bfloat16* __restrict__ BhiT, const __nv_bfloat16* __restrict__ BloT,
              const float* __restrict__ bias, const float* __restrict__ cb,
              float* __restrict__ Cf, __nv_bfloat16* __restrict__ Chi,
              __nv_bfloat16* __restrict__ Clo, int S) {
    extern __shared__ char smem[];
    uint32_t sbase = smem_u32(smem);
    const int tid = threadIdx.x;
    const int lane = tid & 31, wid = tid >> 5;
    const int wm = wid & 3;                  // 0..3 -> 32 rows each
    const int wn = wid >> 2;                 // 0..1 -> 32 cols each
    const int bm = blockIdx.y * 128, bn = blockIdx.x * 64;

    float acc[2][4][4];
    #pragma unroll
    for (int mb = 0; mb < 2; mb++)
        #pragma unroll
        for (int j = 0; j < 4; j++)
            #pragma unroll
            for (int r = 0; r < 4; r++) acc[mb][j][r] = 0.f;

    const int alr = lane & 15, alh = lane >> 4;
    const int bnr = (lane & 7) + (lane >> 4) * 8;
    const int bkh = (lane >> 3) & 1;

    load_chunk(sbase,               Ahi, Alo, BhiT, BloT, bm, bn, 0,  tid);
    load_chunk(sbase + STAGE_BYTES, Ahi, Alo, BhiT, BloT, bm, bn, KC, tid);

    for (int i = 0; i < NCHUNK; i++) {
        if (i == NCHUNK - 1) asm volatile("cp.async.wait_group 0;" ::: "memory");
        else                 asm volatile("cp.async.wait_group 1;" ::: "memory");
        __syncthreads();

        const uint32_t stg   = sbase + (uint32_t)(i & 1) * STAGE_BYTES;
        const uint32_t ahi_b = stg + wm * 32 * TPITCH;
        const uint32_t bhi_b = stg + 2 * TILE_A + wn * 32 * TPITCH;

        #pragma unroll
        for (int kb = 0; kb < 4; kb++) {
            const uint32_t koff = kb * 32;
            uint32_t ah[2][4], al[2][4];
            #pragma unroll
            for (int mb = 0; mb < 2; mb++) {
                uint32_t aaddr = ahi_b + (uint32_t)((mb * 16 + alr) * TPITCH) + koff + alh * 16;
                ldsm_x4(ah[mb], aaddr);
                ldsm_x4(al[mb], aaddr + TILE_A);
            }
            uint32_t bh[2][4], bl[2][4];
            #pragma unroll
            for (int g = 0; g < 2; g++) {
                uint32_t baddr = bhi_b + (uint32_t)((g * 16 + bnr) * TPITCH) + koff + bkh * 16;
                ldsm_x4(bh[g], baddr);
                ldsm_x4(bl[g], baddr + TILE_B);
            }
            #pragma unroll
            for (int mb = 0; mb < 2; mb++)
                #pragma unroll
                for (int g = 0; g < 2; g++)
                    #pragma unroll
                    for (int h = 0; h < 2; h++) {
                        float* d = acc[mb][g * 2 + h];
                        mma_bf16(d, ah[mb], bh[g][2 * h], bh[g][2 * h + 1]);
                        mma_bf16(d, ah[mb], bl[g][2 * h], bl[g][2 * h + 1]);
                        mma_bf16(d, al[mb], bh[g][2 * h], bh[g][2 * h + 1]);
                    }
        }
        __syncthreads();
        if (i + 2 < NCHUNK)
            load_chunk(stg, Ahi, Alo, BhiT, BloT, bm, bn, (i + 2) * KC, tid);
    }

    const int qr = lane >> 2, qc = lane & 3;
    const int batch = bm / S;
    const float* cbr = cb ? (cb + (size_t)batch * DIM) : nullptr;
    #pragma unroll
    for (int mb = 0; mb < 2; mb++) {
        const int row0 = bm + wm * 32 + mb * 16 + qr;
        #pragma unroll
        for (int j = 0; j < 4; j++) {
            const int col = bn + wn * 32 + j * 8 + qc * 2;
            float b0 = bias[col], b1 = bias[col + 1];
            if (cbr) { b0 += cbr[col]; b1 += cbr[col + 1]; }
            float v0 = acc[mb][j][0] + b0, v1 = acc[mb][j][1] + b1;
            float v2 = acc[mb][j][2] + b0, v3 = acc[mb][j][3] + b1;
            if (Cf) {
                *(float2*)(Cf + (size_t)row0 * DIM + col)       = make_float2(v0, v1);
                *(float2*)(Cf + (size_t)(row0 + 8) * DIM + col) = make_float2(v2, v3);
            } else {
                float h0, h1, h2, h3, l0, l1, l2, l3;
                split1(v0, h0, l0); split1(v1, h1, l1);
                split1(v2, h2, l2); split1(v3, h3, l3);
                *(uint32_t*)(Chi + (size_t)row0 * DIM + col)       = pack2(h0, h1);
                *(uint32_t*)(Clo + (size_t)row0 * DIM + col)       = pack2(l0, l1);
                *(uint32_t*)(Chi + (size_t)(row0 + 8) * DIM + col) = pack2(h2, h3);
                *(uint32_t*)(Clo + (size_t)(row0 + 8) * DIM + col) = pack2(l2, l3);
            }
        }
    }
}

// ---------------- flash attention with mma.sync (split-bf16, 3-stage) — UNCHANGED ----------------
#define ABC 64
#define KVP 144
#define ATILE (ABC * KVP)              // 9216
#define ASTAGE (4 * ATILE)             // 36864
#define FA_SMEM (3 * ASTAGE)           // 110592
#define NKBLK (SEQ / ABC)              // 32

__device__ __forceinline__ void load_kv(uint32_t stg,
        const __nv_bfloat16* khi, const __nv_bfloat16* klo,
        const __nv_bfloat16* vhi, const __nv_bfloat16* vlo,
        size_t rowbase, int kbase, int tid) {
    #pragma unroll
    for (int i = 0; i < 8; i++) {
        int idx = tid + i * 256;
        int t = i >> 1;
        int r = (idx >> 3) & 63;
        int c = (idx & 7) << 4;
        const __nv_bfloat16* src = (t == 0) ? khi : (t == 1) ? klo : (t == 2) ? vhi : vlo;
        cp_async16(stg + (uint32_t)(t * ATILE + r * KVP + c),
                   (const char*)(src + rowbase + (size_t)(kbase + r) * DIM) + c);
    }
    cp_commit();
}

__global__ __launch_bounds__(256, 1)
void flash_mma(const __nv_bfloat16* __restrict__ qhi, const __nv_bfloat16* __restrict__ qlo,
               const __nv_bfloat16* __restrict__ khi, const __nv_bfloat16* __restrict__ klo,
               const __nv_bfloat16* __restrict__ vhi, const __nv_bfloat16* __restrict__ vlo,
               __nv_bfloat16* __restrict__ xhi, __nv_bfloat16* __restrict__ xlo) {
    extern __shared__ char smem[];
    uint32_t sbase = smem_u32(smem);
    const int tid = threadIdx.x;
    const int lane = tid & 31, w = tid >> 5;
    const int qr = lane >> 2, qc = lane & 3;

    const int qb = blockIdx.x;
    const int bh = blockIdx.y;
    const int b = bh >> 4, h = bh & 15;
    const size_t rowbase = (size_t)b * SEQ * DIM + h * DK;
    const int r0 = qb * 128 + w * 16 + qr;
    const int r1 = r0 + 8;

    const int bnr = (lane & 7) + (lane >> 4) * 8;
    const int bkh = (lane >> 3) & 1;
    const int vkr = (lane & 7) + (((lane >> 3) & 1) << 3);
    const int vnc = lane >> 4;

    uint32_t qh_[4][4], ql_[4][4];
    {
        const __nv_bfloat16* qhp = qhi + rowbase;
        const __nv_bfloat16* qlp = qlo + rowbase;
        #pragma unroll
        for (int kk = 0; kk < 4; kk++) {
            int c0 = kk * 16 + 2 * qc, c1 = c0 + 8;
            qh_[kk][0] = *(const uint32_t*)(qhp + (size_t)r0 * DIM + c0);
            qh_[kk][1] = *(const uint32_t*)(qhp + (size_t)r1 * DIM + c0);
            qh_[kk][2] = *(const uint32_t*)(qhp + (size_t)r0 * DIM + c1);
            qh_[kk][3] = *(const uint32_t*)(qhp + (size_t)r1 * DIM + c1);
            ql_[kk][0] = *(const uint32_t*)(qlp + (size_t)r0 * DIM + c0);
            ql_[kk][1] = *(const uint32_t*)(qlp + (size_t)r1 * DIM + c0);
            ql_[kk][2] = *(const uint32_t*)(qlp + (size_t)r0 * DIM + c1);
            ql_[kk][3] = *(const uint32_t*)(qlp + (size_t)r1 * DIM + c1);
        }
    }

    load_kv(sbase,          khi, klo, vhi, vlo, rowbase, 0,   tid);
    load_kv(sbase + ASTAGE, khi, klo, vhi, vlo, rowbase, ABC, tid);

    float o[8][4];
    #pragma unroll
    for (int j = 0; j < 8; j++)
        #pragma unroll
        for (int r = 0; r < 4; r++) o[j][r] = 0.f;
    float m0 = -1e30f, m1 = -1e30f, l0 = 0.f, l1 = 0.f;
    const float C = 0.125f * 1.4426950408889634f;

    int stg_i = 0, stg_n = 2;
    for (int blk = 0; blk < NKBLK; blk++) {
        __syncthreads();
        if (blk + 2 < NKBLK)
            load_kv(sbase + (uint32_t)stg_n * ASTAGE, khi, klo, vhi, vlo,
                    rowbase, (blk + 2) * ABC, tid);
        if (blk + 2 < NKBLK)       asm volatile("cp.async.wait_group 2;" ::: "memory");
        else if (blk + 2 == NKBLK) asm volatile("cp.async.wait_group 1;" ::: "memory");
        else                       asm volatile("cp.async.wait_group 0;" ::: "memory");
        __syncthreads();
        const uint32_t stg = sbase + (uint32_t)stg_i * ASTAGE;

        float s[8][4];
        #pragma unroll
        for (int j = 0; j < 8; j++)
            #pragma unroll
            for (int r = 0; r < 4; r++) s[j][r] = 0.f;

        #pragma unroll
        for (int kk = 0; kk < 4; kk++) {
            const uint32_t koff = kk * 32;
            uint32_t bhf[4][4], blf[4][4];
            #pragma unroll
            for (int g = 0; g < 4; g++) {
                uint32_t addr = stg + (uint32_t)((g * 16 + bnr) * KVP) + koff + bkh * 16;
                ldsm_x4(bhf[g], addr);
                ldsm_x4(blf[g], addr + ATILE);
            }
            #pragma unroll
            for (int g = 0; g < 4; g++)
                #pragma unroll
                for (int h2 = 0; h2 < 2; h2++) {
                    float* d = s[g * 2 + h2];
                    mma_bf16(d, qh_[kk], bhf[g][2 * h2], bhf[g][2 * h2 + 1]);
                    mma_bf16(d, qh_[kk], blf[g][2 * h2], blf[g][2 * h2 + 1]);
                    mma_bf16(d, ql_[kk], bhf[g][2 * h2], bhf[g][2 * h2 + 1]);
                }
        }

        float mx0 = -1e30f, mx1 = -1e30f;
        #pragma unroll
        for (int j = 0; j < 8; j++) {
            mx0 = fmaxf(mx0, fmaxf(s[j][0], s[j][1]));
            mx1 = fmaxf(mx1, fmaxf(s[j][2], s[j][3]));
        }
        mx0 = fmaxf(mx0, __shfl_xor_sync(0xFFFFFFFFu, mx0, 1));
        mx0 = fmaxf(mx0, __shfl_xor_sync(0xFFFFFFFFu, mx0, 2));
        mx1 = fmaxf(mx1, __shfl_xor_sync(0xFFFFFFFFu, mx1, 1));
        mx1 = fmaxf(mx1, __shfl_xor_sync(0xFFFFFFFFu, mx1, 2));
        float mn0 = fmaxf(m0, mx0), mn1 = fmaxf(m1, mx1);
        float a0 = ex2((m0 - mn0) * C), a1 = ex2((m1 - mn1) * C);
        m0 = mn0; m1 = mn1;

        float rs0 = 0.f, rs1 = 0.f;
        #pragma unroll
        for (int j = 0; j < 8; j++) {
            s[j][0] = ex2((s[j][0] - m0) * C);
            s[j][1] = ex2((s[j][1] - m0) * C);
            s[j][2] = ex2((s[j][2] - m1) * C);
            s[j][3] = ex2((s[j][3] - m1) * C);
            rs0 += s[j][0] + s[j][1];
            rs1 += s[j][2] + s[j][3];
        }
        rs0 += __shfl_xor_sync(0xFFFFFFFFu, rs0, 1);
        rs0 += __shfl_xor_sync(0xFFFFFFFFu, rs0, 2);
        rs1 += __shfl_xor_sync(0xFFFFFFFFu, rs1, 1);
        rs1 += __shfl_xor_sync(0xFFFFFFFFu, rs1, 2);
        l0 = l0 * a0 + rs0;
        l1 = l1 * a1 + rs1;
        #pragma unroll
        for (int j = 0; j < 8; j++) {
            o[j][0] *= a0; o[j][1] *= a0;
            o[j][2] *= a1; o[j][3] *= a1;
        }

        uint32_t ph[4][4], pl[4][4];
        #pragma unroll
        for (int kk = 0; kk < 4; kk++) {
            float h00, h01, h10, h11, lo00, lo01, lo10, lo11;
            split1(s[2 * kk][0], h00, lo00); split1(s[2 * kk][1], h01, lo01);
            split1(s[2 * kk][2], h10, lo10); split1(s[2 * kk][3], h11, lo11);
            ph[kk][0] = pack2(h00, h01); pl[kk][0] = pack2(lo00, lo01);
            ph[kk][1] = pack2(h10, h11); pl[kk][1] = pack2(lo10, lo11);
            split1(s[2 * kk + 1][0], h00, lo00); split1(s[2 * kk + 1][1], h01, lo01);
            split1(s[2 * kk + 1][2], h10, lo10); split1(s[2 * kk + 1][3], h11, lo11);
            ph[kk][2] = pack2(h00, h01); pl[kk][2] = pack2(lo00, lo01);
            ph[kk][3] = pack2(h10, h11); pl[kk][3] = pack2(lo10, lo11);
        }

        #pragma unroll
        for (int kk = 0; kk < 4; kk++) {
            uint32_t bhf[4][4], blf[4][4];
            #pragma unroll
            for (int g = 0; g < 4; g++) {
                uint32_t addr = stg + 2 * ATILE + (uint32_t)((kk * 16 + vkr) * KVP) + g * 32 + vnc * 16;
                ldsm_x4_t(bhf[g], addr);
                ldsm_x4_t(blf[g], addr + ATILE);
            }
            #pragma unroll
            for (int g = 0; g < 4; g++)
                #pragma unroll
                for (int h2 = 0; h2 < 2; h2++) {
                    float* d = o[g * 2 + h2];
                    mma_bf16(d, ph[kk], bhf[g][2 * h2], bhf[g][2 * h2 + 1]);
                    mma_bf16(d, ph[kk], blf[g][2 * h2], blf[g][2 * h2 + 1]);
                    mma_bf16(d, pl[kk], bhf[g][2 * h2], bhf[g][2 * h2 + 1]);
                }
        }
        stg_i = (stg_i == 2) ? 0 : stg_i + 1;
        stg_n = (stg_n == 2) ? 0 : stg_n + 1;
    }

    const float inv0 = 1.f / l0, inv1 = 1.f / l1;
    #pragma unroll
    for (int j = 0; j < 8; j++) {
        const int col = j * 8 + 2 * qc;
        float v0 = o[j][0] * inv0, v1 = o[j][1] * inv0;
        float v2 = o[j][2] * inv1, v3 = o[j][3] * inv1;
        float h0, h1, h2, h3, lo0, lo1, lo2, lo3;
        split1(v0, h0, lo0); split1(v1, h1, lo1);
        split1(v2, h2, lo2); split1(v3, h3, lo3);
        *(uint32_t*)(xhi + rowbase + (size_t)r0 * DIM + col) = pack2(h0, h1);
        *(uint32_t*)(xlo + rowbase + (size_t)r0 * DIM + col) = pack2(lo0, lo1);
        *(uint32_t*)(xhi + rowbase + (size_t)r1 * DIM + col) = pack2(h2, h3);
        *(uint32_t*)(xlo + rowbase + (size_t)r1 * DIM + col) = pack2(lo2, lo3);
    }
}

// ---------------- launcher ----------------
extern "C" void kernel_launch(void* const* d_in, const int* in_sizes, int n_in,
                              void* d_out, int out_size) {
    const float* query = (const float*)d_in[0];
    const float* key   = (const float*)d_in[1];
    const float* value = (const float*)d_in[2];
    const float* cond  = (const float*)d_in[3];
    const float* Wq = (const float*)d_in[4];
    const float* bq = (const float*)d_in[5];
    const float* Wk = (const float*)d_in[6];
    const float* bk = (const float*)d_in[7];
    const float* Wv = (const float*)d_in[8];
    const float* bv = (const float*)d_in[9];
    const float* Wo = (const float*)d_in[10];
    const float* bo = (const float*)d_in[11];
    const float* Wc1 = (const float*)d_in[12];
    const float* bc1 = (const float*)d_in[13];
    const float* Wc2 = (const float*)d_in[14];
    float* out = (float*)d_out;

    float *hb, *cb;
    __nv_bfloat16 *ahi, *alo, *whi, *wlo;
    __nv_bfloat16 *qhi, *qlo, *khi, *klo, *vhi, *vlo, *xhi, *xlo;
    cudaGetSymbolAddress((void**)&hb, g_h);
    cudaGetSymbolAddress((void**)&cb, g_c);
    cudaGetSymbolAddress((void**)&ahi, g_ahi);
    cudaGetSymbolAddress((void**)&alo, g_alo);
    cudaGetSymbolAddress((void**)&whi, g_whi);
    cudaGetSymbolAddress((void**)&wlo, g_wlo);
    cudaGetSymbolAddress((void**)&qhi, g_qhi);
    cudaGetSymbolAddress((void**)&qlo, g_qlo);
    cudaGetSymbolAddress((void**)&khi, g_khi);
    cudaGetSymbolAddress((void**)&klo, g_klo);
    cudaGetSymbolAddress((void**)&vhi, g_vhi);
    cudaGetSymbolAddress((void**)&vlo, g_vlo);
    cudaGetSymbolAddress((void**)&xhi, g_xhi);
    cudaGetSymbolAddress((void**)&xlo, g_xlo);

    cudaFuncSetAttribute(gemm_mma,  cudaFuncAttributeMaxDynamicSharedMemorySize, GEMM_SMEM);
    cudaFuncSetAttribute(flash_mma, cudaFuncAttributeMaxDynamicSharedMemorySize, FA_SMEM);

    const int n4 = MROWS * DIM / 4;
    dim3 tgrid(DIM / 32, DIM / 32), tblk(32, 8);
    dim3 ggrid(DIM / 64, MROWS / 128);    // (16, 32) = 512 CTAs

    cond_mlp1<<<BATCH, HID>>>(cond, Wc1, bc1, hb);
    cond_mlp2<<<BATCH, DIM>>>(hb, Wc2, cb);

    // Q projection -> split bf16
    split_w_T<<<tgrid, tblk>>>(Wq, whi, wlo);
    split_f32<<<n4 / 256, 256>>>((const float4*)query, ahi, alo, n4);
    gemm_mma<<<ggrid, 256, GEMM_SMEM>>>(ahi, alo, whi, wlo, bq, nullptr, nullptr, qhi, qlo, SEQ);

    // K projection -> split bf16
    split_w_T<<<tgrid, tblk>>>(Wk, whi, wlo);
    split_f32<<<n4 / 256, 256>>>((const float4*)key, ahi, alo, n4);
    gemm_mma<<<ggrid, 256, GEMM_SMEM>>>(ahi, alo, whi, wlo, bk, nullptr, nullptr, khi, klo, SEQ);

    // V projection (+ cond bias) -> split bf16
    split_w_T<<<tgrid, tblk>>>(Wv, whi, wlo);
    split_f32<<<n4 / 256, 256>>>((const float4*)value, ahi, alo, n4);
    gemm_mma<<<ggrid, 256, GEMM_SMEM>>>(ahi, alo, whi, wlo, bv, cb, nullptr, vhi, vlo, SEQ);

    // attention -> split bf16 x
    flash_mma<<<dim3(SEQ / 128, BATCH * HEADS), 256, FA_SMEM>>>(qhi, qlo, khi, klo, vhi, vlo, xhi, xlo);

    // output projection -> fp32 out
    split_w_T<<<tgrid, tblk>>>(Wo, whi, wlo);
    gemm_mma<<<ggrid, 256, GEMM_SMEM>>>(xhi, xlo, whi, wlo, bo, nullptr, out, nullptr, nullptr, SEQ);
}

// round 15
// speedup vs baseline: 1.9980x; 1.9980x over previous
#include <cuda_runtime.h>
#include <cuda_fp16.h>
#include <cstdint>

// Problem constants
#define BATCH 2
#define SEQ   2048
#define DIM   1024
#define HEADS 16
#define DK    64
#define CL    256
#define HID   512
#define MROWS (BATCH*SEQ)   // 4096

// ---------------- scratch (device globals; no allocation allowed) ----------------
__device__ float g_hb[BATCH * HID];
__device__ float g_cb[BATCH * DIM];
__device__ __half g_ah[MROWS * DIM];    // fp16 input activations
__device__ __half g_wh[DIM * DIM];      // fp16 W^T: [N][K]
__device__ __half g_qh[MROWS * DIM];
__device__ __half g_kh[MROWS * DIM];
__device__ __half g_vh[MROWS * DIM];
__device__ __half g_xh[MROWS * DIM];

// ================= PTX helpers (baseline PTX only) =================
__device__ __forceinline__ uint32_t smem_u32(const void* p) {
    uint32_t a;
    asm("{ .reg .u64 t; cvta.to.shared.u64 t, %1; cvt.u32.u64 %0, t; }" : "=r"(a) : "l"(p));
    return a;
}
__device__ __forceinline__ void cp_async16(uint32_t dst, const void* src) {
    asm volatile("cp.async.cg.shared.global [%0], [%1], 16;" :: "r"(dst), "l"(src) : "memory");
}
__device__ __forceinline__ void cp_commit() {
    asm volatile("cp.async.commit_group;" ::: "memory");
}
__device__ __forceinline__ void ldsm_x4(uint32_t* r, uint32_t addr) {
    asm volatile("ldmatrix.sync.aligned.m8n8.x4.shared.b16 {%0,%1,%2,%3}, [%4];"
                 : "=r"(r[0]), "=r"(r[1]), "=r"(r[2]), "=r"(r[3]) : "r"(addr));
}
__device__ __forceinline__ void ldsm_x4_t(uint32_t* r, uint32_t addr) {
    asm volatile("ldmatrix.sync.aligned.m8n8.x4.trans.shared.b16 {%0,%1,%2,%3}, [%4];"
                 : "=r"(r[0]), "=r"(r[1]), "=r"(r[2]), "=r"(r[3]) : "r"(addr));
}
__device__ __forceinline__ void mma_f16(float* d, const uint32_t* a, uint32_t b0, uint32_t b1) {
    asm volatile(
        "mma.sync.aligned.m16n8k16.row.col.f32.f16.f16.f32 "
        "{%0,%1,%2,%3}, {%4,%5,%6,%7}, {%8,%9}, {%0,%1,%2,%3};"
        : "+f"(d[0]), "+f"(d[1]), "+f"(d[2]), "+f"(d[3])
        : "r"(a[0]), "r"(a[1]), "r"(a[2]), "r"(a[3]), "r"(b0), "r"(b1));
}
// pack two fp32 into f16x2: first arg -> low half
__device__ __forceinline__ uint32_t pack2h(float lo, float hi) {
    uint32_t r;
    asm("cvt.rn.f16x2.f32 %0, %1, %2;" : "=r"(r) : "f"(hi), "f"(lo));
    return r;
}
__device__ __forceinline__ float ex2(float x) {
    float r; asm("ex2.approx.f32 %0, %1;" : "=f"(r) : "f"(x)); return r;
}

// ---------------- conversions ----------------
__global__ void to_f16(const float4* __restrict__ x, __half* __restrict__ o, int n4) {
    int i = blockIdx.x * blockDim.x + threadIdx.x;
    if (i >= n4) return;
    float4 v = x[i];
    ((uint32_t*)o)[2 * i]     = pack2h(v.x, v.y);
    ((uint32_t*)o)[2 * i + 1] = pack2h(v.z, v.w);
}

// W [K,N] -> W^T fp16 [N][K]
__global__ void w_T_f16(const float* __restrict__ W, __half* __restrict__ oT) {
    __shared__ float t[32][33];
    int n0 = blockIdx.x * 32, k0 = blockIdx.y * 32;
    int tx = threadIdx.x, ty = threadIdx.y;   // 32 x 8
    #pragma unroll
    for (int i = ty; i < 32; i += 8) t[i][tx] = W[(size_t)(k0 + i) * DIM + n0 + tx];
    __syncthreads();
    #pragma unroll
    for (int i = ty; i < 32; i += 8)
        oT[(size_t)(n0 + i) * DIM + k0 + tx] = __float2half(t[tx][i]);
}

// ---------------- cond MLP (fp32, tiny) ----------------
__global__ void cond_mlp1(const float* __restrict__ cond, const float* __restrict__ Wc1,
                          const float* __restrict__ bc1, float* __restrict__ h) {
    int b = blockIdx.x;
    int j = threadIdx.x;
    float acc = bc1[j];
    const float* cr = cond + b * CL;
    #pragma unroll 8
    for (int k = 0; k < CL; k++) acc = fmaf(cr[k], Wc1[k * HID + j], acc);
    h[b * HID + j] = acc > 0.f ? acc : 0.f;
}
__global__ void cond_mlp2(const float* __restrict__ h, const float* __restrict__ Wc2,
                          float* __restrict__ c) {
    int b = blockIdx.x;
    int n = threadIdx.x;
    float acc = 0.f;
    const float* hr = h + b * HID;
    #pragma unroll 8
    for (int k = 0; k < HID; k++) acc = fmaf(hr[k], Wc2[k * DIM + n], acc);
    c[b * DIM + n] = acc;
}

// ---------------- fp16 mma.sync GEMM (128x128 tile, 2-stage, 2 CTAs/SM) ----------------
#define KC 64
#define NCHUNK (DIM / KC)                // 16
#define TPITCH 144                       // 64 fp16 = 128B + 16 pad
#define TILE_BYTES (128 * TPITCH)        // 18432
#define STAGE_BYTES (2 * TILE_BYTES)     // A + B = 36864
#define GEMM_SMEM (2 * STAGE_BYTES)      // 73728 -> 2 CTAs/SM

__device__ __forceinline__ void load_chunk(uint32_t stg, const __half* A, const __half* BT,
                                           int bm, int bn, int k0, int tid) {
    #pragma unroll
    for (int i = 0; i < 8; i++) {
        int idx = tid + i * 256;             // 0..2047
        int tile = idx >> 10;                // 0=A, 1=B
        int r = (idx >> 3) & 127;
        int c = (idx & 7) << 4;              // byte col
        const __half* src = tile ? BT : A;
        int rb = tile ? bn : bm;
        cp_async16(stg + (uint32_t)(tile * TILE_BYTES + r * TPITCH + c),
                   (const char*)(src + (size_t)(rb + r) * DIM + k0) + c);
    }
    cp_commit();
}

// Cf!=null: fp32 output. Else: fp16 output to Ch.
__global__ __launch_bounds__(256, 2)
void gemm_mma(const __half* __restrict__ A, const __half* __restrict__ BT,
              const float* __restrict__ bias, const float* __restrict__ cb,
              float* __restrict__ Cf, __half* __restrict__ Ch, int S) {
    extern __shared__ char smem[];
    uint32_t sbase = smem_u32(smem);
    const int tid = threadIdx.x;
    const int lane = tid & 31, wid = tid >> 5;
    const int wm = wid & 3;                  // 0..3 -> 32 rows
    const int wn = wid >> 2;                 // 0..1 -> 64 cols
    const int bm = blockIdx.y * 128, bn = blockIdx.x * 128;

    float acc[2][8][4];
    #pragma unroll
    for (int mb = 0; mb < 2; mb++)
        #pragma unroll
        for (int j = 0; j < 8; j++)
            #pragma unroll
            for (int r = 0; r < 4; r++) acc[mb][j][r] = 0.f;

    const int alr = lane & 15, alh = lane >> 4;
    const int bnr = (lane & 7) + (lane >> 4) * 8;
    const int bkh = (lane >> 3) & 1;

    load_chunk(sbase,               A, BT, bm, bn, 0,  tid);
    load_chunk(sbase + STAGE_BYTES, A, BT, bm, bn, KC, tid);

    for (int i = 0; i < NCHUNK; i++) {
        if (i == NCHUNK - 1) asm volatile("cp.async.wait_group 0;" ::: "memory");
        else                 asm volatile("cp.async.wait_group 1;" ::: "memory");
        __syncthreads();

        const uint32_t stg  = sbase + (uint32_t)(i & 1) * STAGE_BYTES;
        const uint32_t a_b  = stg + wm * 32 * TPITCH;
        const uint32_t b_b  = stg + TILE_BYTES + wn * 64 * TPITCH;

        #pragma unroll
        for (int kb = 0; kb < 4; kb++) {
            const uint32_t koff = kb * 32;
            uint32_t ah[2][4];
            #pragma unroll
            for (int mb = 0; mb < 2; mb++)
                ldsm_x4(ah[mb], a_b + (uint32_t)((mb * 16 + alr) * TPITCH) + koff + alh * 16);
            uint32_t bh[4][4];
            #pragma unroll
            for (int g = 0; g < 4; g++)
                ldsm_x4(bh[g], b_b + (uint32_t)((g * 16 + bnr) * TPITCH) + koff + bkh * 16);
            #pragma unroll
            for (int mb = 0; mb < 2; mb++)
                #pragma unroll
                for (int g = 0; g < 4; g++)
                    #pragma unroll
                    for (int h = 0; h < 2; h++)
                        mma_f16(acc[mb][g * 2 + h], ah[mb], bh[g][2 * h], bh[g][2 * h + 1]);
        }
        __syncthreads();
        if (i + 2 < NCHUNK)
            load_chunk(stg, A, BT, bm, bn, (i + 2) * KC, tid);
    }

    const int qr = lane >> 2, qc = lane & 3;
    const int batch = bm / S;
    const float* cbr = cb ? (cb + (size_t)batch * DIM) : nullptr;
    #pragma unroll
    for (int mb = 0; mb < 2; mb++) {
        const int row0 = bm + wm * 32 + mb * 16 + qr;
        #pragma unroll
        for (int j = 0; j < 8; j++) {
            const int col = bn + wn * 64 + j * 8 + qc * 2;
            float b0 = bias[col], b1 = bias[col + 1];
            if (cbr) { b0 += cbr[col]; b1 += cbr[col + 1]; }
            float v0 = acc[mb][j][0] + b0, v1 = acc[mb][j][1] + b1;
            float v2 = acc[mb][j][2] + b0, v3 = acc[mb][j][3] + b1;
            if (Cf) {
                *(float2*)(Cf + (size_t)row0 * DIM + col)       = make_float2(v0, v1);
                *(float2*)(Cf + (size_t)(row0 + 8) * DIM + col) = make_float2(v2, v3);
            } else {
                *(uint32_t*)(Ch + (size_t)row0 * DIM + col)       = pack2h(v0, v1);
                *(uint32_t*)(Ch + (size_t)(row0 + 8) * DIM + col) = pack2h(v2, v3);
            }
        }
    }
}

// ---------------- flash attention, fp16 mma.sync ----------------
#define ABC 64
#define KVP 144
#define ATILE (ABC * KVP)              // 9216
#define ASTAGE (2 * ATILE)             // K + V = 18432
#define FA_SMEM (3 * ASTAGE)           // 55296
#define NKBLK (SEQ / ABC)              // 32

__device__ __forceinline__ void load_kv(uint32_t stg,
        const __half* kh, const __half* vh, size_t rowbase, int kbase, int tid) {
    #pragma unroll
    for (int i = 0; i < 4; i++) {
        int idx = tid + i * 256;              // 0..1023
        int t = idx >> 9;                     // 0=K, 1=V
        int r = (idx >> 3) & 63;
        int c = (idx & 7) << 4;
        const __half* src = t ? vh : kh;
        cp_async16(stg + (uint32_t)(t * ATILE + r * KVP + c),
                   (const char*)(src + rowbase + (size_t)(kbase + r) * DIM) + c);
    }
    cp_commit();
}

__global__ __launch_bounds__(256, 1)
void flash_mma(const __half* __restrict__ qh, const __half* __restrict__ kh,
               const __half* __restrict__ vh, __half* __restrict__ xh) {
    extern __shared__ char smem[];
    uint32_t sbase = smem_u32(smem);
    const int tid = threadIdx.x;
    const int lane = tid & 31, w = tid >> 5;
    const int qr = lane >> 2, qc = lane & 3;

    const int qb = blockIdx.x;
    const int bh = blockIdx.y;
    const int b = bh >> 4, h = bh & 15;
    const size_t rowbase = (size_t)b * SEQ * DIM + h * DK;
    const int r0 = qb * 128 + w * 16 + qr;
    const int r1 = r0 + 8;

    const int bnr = (lane & 7) + (lane >> 4) * 8;
    const int bkh = (lane >> 3) & 1;
    const int vkr = (lane & 7) + (((lane >> 3) & 1) << 3);
    const int vnc = lane >> 4;

    // Q fragments (registers)
    uint32_t qf[4][4];
    {
        const __half* qp = qh + rowbase;
        #pragma unroll
        for (int kk = 0; kk < 4; kk++) {
            int c0 = kk * 16 + 2 * qc, c1 = c0 + 8;
            qf[kk][0] = *(const uint32_t*)(qp + (size_t)r0 * DIM + c0);
            qf[kk][1] = *(const uint32_t*)(qp + (size_t)r1 * DIM + c0);
            qf[kk][2] = *(const uint32_t*)(qp + (size_t)r0 * DIM + c1);
            qf[kk][3] = *(const uint32_t*)(qp + (size_t)r1 * DIM + c1);
        }
    }

    load_kv(sbase,          kh, vh, rowbase, 0,   tid);
    load_kv(sbase + ASTAGE, kh, vh, rowbase, ABC, tid);

    float o[8][4];
    #pragma unroll
    for (int j = 0; j < 8; j++)
        #pragma unroll
        for (int r = 0; r < 4; r++) o[j][r] = 0.f;
    float m0 = -1e30f, m1 = -1e30f, l0 = 0.f, l1 = 0.f;
    const float C = 0.125f * 1.4426950408889634f;

    int stg_i = 0, stg_n = 2;
    for (int blk = 0; blk < NKBLK; blk++) {
        __syncthreads();
        if (blk + 2 < NKBLK)
            load_kv(sbase + (uint32_t)stg_n * ASTAGE, kh, vh, rowbase, (blk + 2) * ABC, tid);
        if (blk + 2 < NKBLK)       asm volatile("cp.async.wait_group 2;" ::: "memory");
        else if (blk + 2 == NKBLK) asm volatile("cp.async.wait_group 1;" ::: "memory");
        else                       asm volatile("cp.async.wait_group 0;" ::: "memory");
        __syncthreads();
        const uint32_t stg = sbase + (uint32_t)stg_i * ASTAGE;

        // ---- S = Q K^T ----
        float s[8][4];
        #pragma unroll
        for (int j = 0; j < 8; j++)
            #pragma unroll
            for (int r = 0; r < 4; r++) s[j][r] = 0.f;

        #pragma unroll
        for (int kk = 0; kk < 4; kk++) {
            const uint32_t koff = kk * 32;
            uint32_t bf[4][4];
            #pragma unroll
            for (int g = 0; g < 4; g++)
                ldsm_x4(bf[g], stg + (uint32_t)((g * 16 + bnr) * KVP) + koff + bkh * 16);
            #pragma unroll
            for (int g = 0; g < 4; g++)
                #pragma unroll
                for (int h2 = 0; h2 < 2; h2++)
                    mma_f16(s[g * 2 + h2], qf[kk], bf[g][2 * h2], bf[g][2 * h2 + 1]);
        }

        // ---- online softmax ----
        float mx0 = -1e30f, mx1 = -1e30f;
        #pragma unroll
        for (int j = 0; j < 8; j++) {
            mx0 = fmaxf(mx0, fmaxf(s[j][0], s[j][1]));
            mx1 = fmaxf(mx1, fmaxf(s[j][2], s[j][3]));
        }
        mx0 = fmaxf(mx0, __shfl_xor_sync(0xFFFFFFFFu, mx0, 1));
        mx0 = fmaxf(mx0, __shfl_xor_sync(0xFFFFFFFFu, mx0, 2));
        mx1 = fmaxf(mx1, __shfl_xor_sync(0xFFFFFFFFu, mx1, 1));
        mx1 = fmaxf(mx1, __shfl_xor_sync(0xFFFFFFFFu, mx1, 2));
        float mn0 = fmaxf(m0, mx0), mn1 = fmaxf(m1, mx1);
        float a0 = ex2((m0 - mn0) * C), a1 = ex2((m1 - mn1) * C);
        m0 = mn0; m1 = mn1;

        float rs0 = 0.f, rs1 = 0.f;
        #pragma unroll
        for (int j = 0; j < 8; j++) {
            s[j][0] = ex2((s[j][0] - m0) * C);
            s[j][1] = ex2((s[j][1] - m0) * C);
            s[j][2] = ex2((s[j][2] - m1) * C);
            s[j][3] = ex2((s[j][3] - m1) * C);
            rs0 += s[j][0] + s[j][1];
            rs1 += s[j][2] + s[j][3];
        }
        rs0 += __shfl_xor_sync(0xFFFFFFFFu, rs0, 1);
        rs0 += __shfl_xor_sync(0xFFFFFFFFu, rs0, 2);
        rs1 += __shfl_xor_sync(0xFFFFFFFFu, rs1, 1);
        rs1 += __shfl_xor_sync(0xFFFFFFFFu, rs1, 2);
        l0 = l0 * a0 + rs0;
        l1 = l1 * a1 + rs1;
        #pragma unroll
        for (int j = 0; j < 8; j++) {
            o[j][0] *= a0; o[j][1] *= a0;
            o[j][2] *= a1; o[j][3] *= a1;
        }

        // ---- P -> fp16 A-fragments (register-only) ----
        uint32_t pf[4][4];
        #pragma unroll
        for (int kk = 0; kk < 4; kk++) {
            pf[kk][0] = pack2h(s[2 * kk][0],     s[2 * kk][1]);
            pf[kk][1] = pack2h(s[2 * kk][2],     s[2 * kk][3]);
            pf[kk][2] = pack2h(s[2 * kk + 1][0], s[2 * kk + 1][1]);
            pf[kk][3] = pack2h(s[2 * kk + 1][2], s[2 * kk + 1][3]);
        }

        // ---- O += P V (V via ldmatrix.trans) ----
        #pragma unroll
        for (int kk = 0; kk < 4; kk++) {
            uint32_t bf[4][4];
            #pragma unroll
            for (int g = 0; g < 4; g++)
                ldsm_x4_t(bf[g], stg + ATILE + (uint32_t)((kk * 16 + vkr) * KVP) + g * 32 + vnc * 16);
            #pragma unroll
            for (int g = 0; g < 4; g++)
                #pragma unroll
                for (int h2 = 0; h2 < 2; h2++)
                    mma_f16(o[g * 2 + h2], pf[kk], bf[g][2 * h2], bf[g][2 * h2 + 1]);
        }
        stg_i = (stg_i == 2) ? 0 : stg_i + 1;
        stg_n = (stg_n == 2) ? 0 : stg_n + 1;
    }

    // ---- epilogue ----
    const float inv0 = 1.f / l0, inv1 = 1.f / l1;
    #pragma unroll
    for (int j = 0; j < 8; j++) {
        const int col = j * 8 + 2 * qc;
        *(uint32_t*)(xh + rowbase + (size_t)r0 * DIM + col) = pack2h(o[j][0] * inv0, o[j][1] * inv0);
        *(uint32_t*)(xh + rowbase + (size_t)r1 * DIM + col) = pack2h(o[j][2] * inv1, o[j][3] * inv1);
    }
}

// ---------------- launcher ----------------
extern "C" void kernel_launch(void* const* d_in, const int* in_sizes, int n_in,
                              void* d_out, int out_size) {
    const float* query = (const float*)d_in[0];
    const float* key   = (const float*)d_in[1];
    const float* value = (const float*)d_in[2];
    const float* cond  = (const float*)d_in[3];
    const float* Wq = (const float*)d_in[4];
    const float* bq = (const float*)d_in[5];
    const float* Wk = (const float*)d_in[6];
    const float* bk = (const float*)d_in[7];
    const float* Wv = (const float*)d_in[8];
    const float* bv = (const float*)d_in[9];
    const float* Wo = (const float*)d_in[10];
    const float* bo = (const float*)d_in[11];
    const float* Wc1 = (const float*)d_in[12];
    const float* bc1 = (const float*)d_in[13];
    const float* Wc2 = (const float*)d_in[14];
    float* out = (float*)d_out;

    float *hb, *cb;
    __half *ah, *wh, *qh, *kh, *vh, *xh;
    cudaGetSymbolAddress((void**)&hb, g_hb);
    cudaGetSymbolAddress((void**)&cb, g_cb);
    cudaGetSymbolAddress((void**)&ah, g_ah);
    cudaGetSymbolAddress((void**)&wh, g_wh);
    cudaGetSymbolAddress((void**)&qh, g_qh);
    cudaGetSymbolAddress((void**)&kh, g_kh);
    cudaGetSymbolAddress((void**)&vh, g_vh);
    cudaGetSymbolAddress((void**)&xh, g_xh);

    cudaFuncSetAttribute(gemm_mma,  cudaFuncAttributeMaxDynamicSharedMemorySize, GEMM_SMEM);
    cudaFuncSetAttribute(flash_mma, cudaFuncAttributeMaxDynamicSharedMemorySize, FA_SMEM);

    const int n4 = MROWS * DIM / 4;
    dim3 tgrid(DIM / 32, DIM / 32), tblk(32, 8);
    dim3 ggrid(DIM / 128, MROWS / 128);   // (8, 32)

    cond_mlp1<<<BATCH, HID>>>(cond, Wc1, bc1, hb);
    cond_mlp2<<<BATCH, DIM>>>(hb, Wc2, cb);

    // Q projection
    w_T_f16<<<tgrid, tblk>>>(Wq, wh);
    to_f16<<<n4 / 256, 256>>>((const float4*)query, ah, n4);
    gemm_mma<<<ggrid, 256, GEMM_SMEM>>>(ah, wh, bq, nullptr, nullptr, qh, SEQ);

    // K projection
    w_T_f16<<<tgrid, tblk>>>(Wk, wh);
    to_f16<<<n4 / 256, 256>>>((const float4*)key, ah, n4);
    gemm_mma<<<ggrid, 256, GEMM_SMEM>>>(ah, wh, bk, nullptr, nullptr, kh, SEQ);

    // V projection (+ cond bias)
    w_T_f16<<<tgrid, tblk>>>(Wv, wh);
    to_f16<<<n4 / 256, 256>>>((const float4*)value, ah, n4);
    gemm_mma<<<ggrid, 256, GEMM_SMEM>>>(ah, wh, bv, cb, nullptr, vh, SEQ);

    // attention
    flash_mma<<<dim3(SEQ / 128, BATCH * HEADS), 256, FA_SMEM>>>(qh, kh, vh, xh);

    // output projection -> fp32 out
    w_T_f16<<<tgrid, tblk>>>(Wo, wh);
    gemm_mma<<<ggrid, 256, GEMM_SMEM>>>(xh, wh, bo, nullptr, out, nullptr, SEQ);
}

// round 16
// speedup vs baseline: 2.1265x; 1.0643x over previous
#include <cuda_runtime.h>
#include <cuda_fp16.h>
#include <cstdint>

// Problem constants
#define BATCH 2
#define SEQ   2048
#define DIM   1024
#define HEADS 16
#define DK    64
#define CL    256
#define HID   512
#define MROWS (BATCH*SEQ)   // 4096

// ---------------- scratch (device globals; no allocation allowed) ----------------
__device__ float g_hb[BATCH * HID];
__device__ float g_cb[BATCH * DIM];
__device__ __half g_ah3[3 * MROWS * DIM];   // fp16 query|key|value inputs
__device__ __half g_wh4[4 * DIM * DIM];     // fp16 W^T for q,k,v,o: [N][K]
__device__ __half g_qkv[3 * MROWS * DIM];   // fp16 q|k|v projected
__device__ __half g_xh[MROWS * DIM];        // fp16 attention output

// ================= PTX helpers (baseline PTX only) =================
__device__ __forceinline__ uint32_t smem_u32(const void* p) {
    uint32_t a;
    asm("{ .reg .u64 t; cvta.to.shared.u64 t, %1; cvt.u32.u64 %0, t; }" : "=r"(a) : "l"(p));
    return a;
}
__device__ __forceinline__ void cp_async16(uint32_t dst, const void* src) {
    asm volatile("cp.async.cg.shared.global [%0], [%1], 16;" :: "r"(dst), "l"(src) : "memory");
}
__device__ __forceinline__ void cp_commit() {
    asm volatile("cp.async.commit_group;" ::: "memory");
}
__device__ __forceinline__ void ldsm_x4(uint32_t* r, uint32_t addr) {
    asm volatile("ldmatrix.sync.aligned.m8n8.x4.shared.b16 {%0,%1,%2,%3}, [%4];"
                 : "=r"(r[0]), "=r"(r[1]), "=r"(r[2]), "=r"(r[3]) : "r"(addr));
}
__device__ __forceinline__ void ldsm_x4_t(uint32_t* r, uint32_t addr) {
    asm volatile("ldmatrix.sync.aligned.m8n8.x4.trans.shared.b16 {%0,%1,%2,%3}, [%4];"
                 : "=r"(r[0]), "=r"(r[1]), "=r"(r[2]), "=r"(r[3]) : "r"(addr));
}
__device__ __forceinline__ void mma_f16(float* d, const uint32_t* a, uint32_t b0, uint32_t b1) {
    asm volatile(
        "mma.sync.aligned.m16n8k16.row.col.f32.f16.f16.f32 "
        "{%0,%1,%2,%3}, {%4,%5,%6,%7}, {%8,%9}, {%0,%1,%2,%3};"
        : "+f"(d[0]), "+f"(d[1]), "+f"(d[2]), "+f"(d[3])
        : "r"(a[0]), "r"(a[1]), "r"(a[2]), "r"(a[3]), "r"(b0), "r"(b1));
}
__device__ __forceinline__ uint32_t pack2h(float lo, float hi) {
    uint32_t r;
    asm("cvt.rn.f16x2.f32 %0, %1, %2;" : "=r"(r) : "f"(hi), "f"(lo));
    return r;
}
__device__ __forceinline__ float ex2(float x) {
    float r; asm("ex2.approx.f32 %0, %1;" : "=f"(r) : "f"(x)); return r;
}

// ---------------- conversions (merged) ----------------
// all three inputs in one launch: grid (n4/256, 3)
__global__ void conv3(const float4* __restrict__ a0, const float4* __restrict__ a1,
                      const float4* __restrict__ a2, __half* __restrict__ o, int n4) {
    int z = blockIdx.y;
    const float4* src = (z == 0) ? a0 : (z == 1) ? a1 : a2;
    __half* dst = o + (size_t)z * MROWS * DIM;
    int i = blockIdx.x * blockDim.x + threadIdx.x;
    if (i >= n4) return;
    float4 v = src[i];
    ((uint32_t*)dst)[2 * i]     = pack2h(v.x, v.y);
    ((uint32_t*)dst)[2 * i + 1] = pack2h(v.z, v.w);
}

// all four weights W [K,N] -> W^T fp16 [N][K], grid (32,32,4)
__global__ void wT4(const float* __restrict__ w0, const float* __restrict__ w1,
                    const float* __restrict__ w2, const float* __restrict__ w3,
                    __half* __restrict__ oT) {
    __shared__ float t[32][33];
    int z = blockIdx.z;
    const float* W = (z == 0) ? w0 : (z == 1) ? w1 : (z == 2) ? w2 : w3;
    __half* dst = oT + (size_t)z * DIM * DIM;
    int n0 = blockIdx.x * 32, k0 = blockIdx.y * 32;
    int tx = threadIdx.x, ty = threadIdx.y;   // 32 x 8
    #pragma unroll
    for (int i = ty; i < 32; i += 8) t[i][tx] = W[(size_t)(k0 + i) * DIM + n0 + tx];
    __syncthreads();
    #pragma unroll
    for (int i = ty; i < 32; i += 8)
        dst[(size_t)(n0 + i) * DIM + k0 + tx] = __float2half(t[tx][i]);
}

// ---------------- cond MLP (fp32, tiny) ----------------
__global__ void cond_mlp1(const float* __restrict__ cond, const float* __restrict__ Wc1,
                          const float* __restrict__ bc1, float* __restrict__ h) {
    int b = blockIdx.x;
    int j = blockIdx.y * 128 + threadIdx.x;
    float acc = bc1[j];
    const float* cr = cond + b * CL;
    #pragma unroll 8
    for (int k = 0; k < CL; k++) acc = fmaf(cr[k], Wc1[k * HID + j], acc);
    g_hb[b * HID + j] = acc > 0.f ? acc : 0.f;
    (void)h;
}
__global__ void cond_mlp2(const float* __restrict__ Wc2, float* __restrict__ c) {
    int b = blockIdx.x;
    int n = blockIdx.y * 128 + threadIdx.x;
    float acc = 0.f;
    const float* hr = g_hb + b * HID;
    #pragma unroll 8
    for (int k = 0; k < HID; k++) acc = fmaf(hr[k], Wc2[k * DIM + n], acc);
    c[b * DIM + n] = acc;
}

// ---------------- fp16 mma.sync GEMM (128x128 tile, z-batched) ----------------
#define KC 64
#define NCHUNK (DIM / KC)                // 16
#define TPITCH 144
#define TILE_BYTES (128 * TPITCH)        // 18432
#define STAGE_BYTES (2 * TILE_BYTES)     // 36864
#define GEMM_SMEM (2 * STAGE_BYTES)      // 73728

__device__ __forceinline__ void load_chunk(uint32_t stg, const __half* A, const __half* BT,
                                           int bm, int bn, int k0, int tid) {
    #pragma unroll
    for (int i = 0; i < 8; i++) {
        int idx = tid + i * 256;
        int tile = idx >> 10;                // 0=A, 1=B
        int r = (idx >> 3) & 127;
        int c = (idx & 7) << 4;
        const __half* src = tile ? BT : A;
        int rb = tile ? bn : bm;
        cp_async16(stg + (uint32_t)(tile * TILE_BYTES + r * TPITCH + c),
                   (const char*)(src + (size_t)(rb + r) * DIM + k0) + c);
    }
    cp_commit();
}

// grid.z selects (A, W, bias, output). Cf!=null -> fp32 out (z must be 0 use b0).
__global__ __launch_bounds__(256, 2)
void gemm_mma(const __half* __restrict__ Abase, const __half* __restrict__ Wbase,
              const float* __restrict__ b0, const float* __restrict__ b1,
              const float* __restrict__ b2, const float* __restrict__ cb,
              float* __restrict__ Cf, __half* __restrict__ Chbase, int S) {
    extern __shared__ char smem[];
    uint32_t sbase = smem_u32(smem);
    const int tid = threadIdx.x;
    const int lane = tid & 31, wid = tid >> 5;
    const int wm = wid & 3;
    const int wn = wid >> 2;
    const int bm = blockIdx.y * 128, bn = blockIdx.x * 128;
    const int z = blockIdx.z;

    const __half* A  = Abase + (size_t)z * MROWS * DIM;
    const __half* BT = Wbase + (size_t)z * DIM * DIM;
    const float* bias = (z == 0) ? b0 : (z == 1) ? b1 : b2;
    const float* cbz  = (cb && z == 2) ? cb : nullptr;

    float acc[2][8][4];
    #pragma unroll
    for (int mb = 0; mb < 2; mb++)
        #pragma unroll
        for (int j = 0; j < 8; j++)
            #pragma unroll
            for (int r = 0; r < 4; r++) acc[mb][j][r] = 0.f;

    const int alr = lane & 15, alh = lane >> 4;
    const int bnr = (lane & 7) + (lane >> 4) * 8;
    const int bkh = (lane >> 3) & 1;

    load_chunk(sbase,               A, BT, bm, bn, 0,  tid);
    load_chunk(sbase + STAGE_BYTES, A, BT, bm, bn, KC, tid);

    for (int i = 0; i < NCHUNK; i++) {
        if (i == NCHUNK - 1) asm volatile("cp.async.wait_group 0;" ::: "memory");
        else                 asm volatile("cp.async.wait_group 1;" ::: "memory");
        __syncthreads();

        const uint32_t stg = sbase + (uint32_t)(i & 1) * STAGE_BYTES;
        const uint32_t a_b = stg + wm * 32 * TPITCH;
        const uint32_t b_b = stg + TILE_BYTES + wn * 64 * TPITCH;

        #pragma unroll
        for (int kb = 0; kb < 4; kb++) {
            const uint32_t koff = kb * 32;
            uint32_t ah[2][4];
            #pragma unroll
            for (int mb = 0; mb < 2; mb++)
                ldsm_x4(ah[mb], a_b + (uint32_t)((mb * 16 + alr) * TPITCH) + koff + alh * 16);
            uint32_t bh[4][4];
            #pragma unroll
            for (int g = 0; g < 4; g++)
                ldsm_x4(bh[g], b_b + (uint32_t)((g * 16 + bnr) * TPITCH) + koff + bkh * 16);
            #pragma unroll
            for (int mb = 0; mb < 2; mb++)
                #pragma unroll
                for (int g = 0; g < 4; g++)
                    #pragma unroll
                    for (int h = 0; h < 2; h++)
                        mma_f16(acc[mb][g * 2 + h], ah[mb], bh[g][2 * h], bh[g][2 * h + 1]);
        }
        __syncthreads();
        if (i + 2 < NCHUNK)
            load_chunk(stg, A, BT, bm, bn, (i + 2) * KC, tid);
    }

    const int qr = lane >> 2, qc = lane & 3;
    const int batch = bm / S;
    const float* cbr = cbz ? (cbz + (size_t)batch * DIM) : nullptr;
    __half* Ch = Chbase ? (Chbase + (size_t)z * MROWS * DIM) : nullptr;
    #pragma unroll
    for (int mb = 0; mb < 2; mb++) {
        const int row0 = bm + wm * 32 + mb * 16 + qr;
        #pragma unroll
        for (int j = 0; j < 8; j++) {
            const int col = bn + wn * 64 + j * 8 + qc * 2;
            float b0v = bias[col], b1v = bias[col + 1];
            if (cbr) { b0v += cbr[col]; b1v += cbr[col + 1]; }
            float v0 = acc[mb][j][0] + b0v, v1 = acc[mb][j][1] + b1v;
            float v2 = acc[mb][j][2] + b0v, v3 = acc[mb][j][3] + b1v;
            if (Cf) {
                *(float2*)(Cf + (size_t)row0 * DIM + col)       = make_float2(v0, v1);
                *(float2*)(Cf + (size_t)(row0 + 8) * DIM + col) = make_float2(v2, v3);
            } else {
                *(uint32_t*)(Ch + (size_t)row0 * DIM + col)       = pack2h(v0, v1);
                *(uint32_t*)(Ch + (size_t)(row0 + 8) * DIM + col) = pack2h(v2, v3);
            }
        }
    }
}

// ---------------- flash attention, fp16 mma.sync, Bc=128 ----------------
#define ABC 128
#define KVP 144
#define ATILE (ABC * KVP)              // 18432
#define ASTAGE (2 * ATILE)             // 36864
#define FA_SMEM (3 * ASTAGE)           // 110592
#define NKBLK (SEQ / ABC)              // 16

__device__ __forceinline__ void load_kv(uint32_t stg,
        const __half* kh, const __half* vh, size_t rowbase, int kbase, int tid) {
    #pragma unroll
    for (int i = 0; i < 8; i++) {
        int idx = tid + i * 256;              // 0..2047
        int t = idx >> 10;                    // 0=K, 1=V
        int r = (idx >> 3) & 127;
        int c = (idx & 7) << 4;
        const __half* src = t ? vh : kh;
        cp_async16(stg + (uint32_t)(t * ATILE + r * KVP + c),
                   (const char*)(src + rowbase + (size_t)(kbase + r) * DIM) + c);
    }
    cp_commit();
}

__global__ __launch_bounds__(256, 1)
void flash_mma(const __half* __restrict__ qh, const __half* __restrict__ kh,
               const __half* __restrict__ vh, __half* __restrict__ xh) {
    extern __shared__ char smem[];
    uint32_t sbase = smem_u32(smem);
    const int tid = threadIdx.x;
    const int lane = tid & 31, w = tid >> 5;
    const int qr = lane >> 2, qc = lane & 3;

    const int qb = blockIdx.x;
    const int bh = blockIdx.y;
    const int b = bh >> 4, h = bh & 15;
    const size_t rowbase = (size_t)b * SEQ * DIM + h * DK;
    const int r0 = qb * 128 + w * 16 + qr;
    const int r1 = r0 + 8;

    const int bnr = (lane & 7) + (lane >> 4) * 8;
    const int bkh = (lane >> 3) & 1;
    const int vkr = (lane & 7) + (((lane >> 3) & 1) << 3);
    const int vnc = lane >> 4;

    uint32_t qf[4][4];
    {
        const __half* qp = qh + rowbase;
        #pragma unroll
        for (int kk = 0; kk < 4; kk++) {
            int c0 = kk * 16 + 2 * qc, c1 = c0 + 8;
            qf[kk][0] = *(const uint32_t*)(qp + (size_t)r0 * DIM + c0);
            qf[kk][1] = *(const uint32_t*)(qp + (size_t)r1 * DIM + c0);
            qf[kk][2] = *(const uint32_t*)(qp + (size_t)r0 * DIM + c1);
            qf[kk][3] = *(const uint32_t*)(qp + (size_t)r1 * DIM + c1);
        }
    }

    load_kv(sbase,          kh, vh, rowbase, 0,   tid);
    load_kv(sbase + ASTAGE, kh, vh, rowbase, ABC, tid);

    float o[8][4];
    #pragma unroll
    for (int j = 0; j < 8; j++)
        #pragma unroll
        for (int r = 0; r < 4; r++) o[j][r] = 0.f;
    float m0 = -1e30f, m1 = -1e30f, l0 = 0.f, l1 = 0.f;
    const float C = 0.125f * 1.4426950408889634f;

    int stg_i = 0, stg_n = 2;
    for (int blk = 0; blk < NKBLK; blk++) {
        __syncthreads();
        if (blk + 2 < NKBLK)
            load_kv(sbase + (uint32_t)stg_n * ASTAGE, kh, vh, rowbase, (blk + 2) * ABC, tid);
        if (blk + 2 < NKBLK)       asm volatile("cp.async.wait_group 2;" ::: "memory");
        else if (blk + 2 == NKBLK) asm volatile("cp.async.wait_group 1;" ::: "memory");
        else                       asm volatile("cp.async.wait_group 0;" ::: "memory");
        __syncthreads();
        const uint32_t stg = sbase + (uint32_t)stg_i * ASTAGE;

        // ---- S = Q K^T : 16 n-tiles of 8 cols ----
        float s[16][4];
        #pragma unroll
        for (int j = 0; j < 16; j++)
            #pragma unroll
            for (int r = 0; r < 4; r++) s[j][r] = 0.f;

        #pragma unroll
        for (int kk = 0; kk < 4; kk++) {
            const uint32_t koff = kk * 32;
            #pragma unroll
            for (int g = 0; g < 8; g++) {
                uint32_t bf[4];
                ldsm_x4(bf, stg + (uint32_t)((g * 16 + bnr) * KVP) + koff + bkh * 16);
                mma_f16(s[g * 2 + 0], qf[kk], bf[0], bf[1]);
                mma_f16(s[g * 2 + 1], qf[kk], bf[2], bf[3]);
            }
        }

        // ---- online softmax ----
        float mx0 = -1e30f, mx1 = -1e30f;
        #pragma unroll
        for (int j = 0; j < 16; j++) {
            mx0 = fmaxf(mx0, fmaxf(s[j][0], s[j][1]));
            mx1 = fmaxf(mx1, fmaxf(s[j][2], s[j][3]));
        }
        mx0 = fmaxf(mx0, __shfl_xor_sync(0xFFFFFFFFu, mx0, 1));
        mx0 = fmaxf(mx0, __shfl_xor_sync(0xFFFFFFFFu, mx0, 2));
        mx1 = fmaxf(mx1, __shfl_xor_sync(0xFFFFFFFFu, mx1, 1));
        mx1 = fmaxf(mx1, __shfl_xor_sync(0xFFFFFFFFu, mx1, 2));
        float mn0 = fmaxf(m0, mx0), mn1 = fmaxf(m1, mx1);
        float a0 = ex2((m0 - mn0) * C), a1 = ex2((m1 - mn1) * C);
        m0 = mn0; m1 = mn1;

        float rs0 = 0.f, rs1 = 0.f;
        #pragma unroll
        for (int j = 0; j < 16; j++) {
            s[j][0] = ex2((s[j][0] - m0) * C);
            s[j][1] = ex2((s[j][1] - m0) * C);
            s[j][2] = ex2((s[j][2] - m1) * C);
            s[j][3] = ex2((s[j][3] - m1) * C);
            rs0 += s[j][0] + s[j][1];
            rs1 += s[j][2] + s[j][3];
        }
        rs0 += __shfl_xor_sync(0xFFFFFFFFu, rs0, 1);
        rs0 += __shfl_xor_sync(0xFFFFFFFFu, rs0, 2);
        rs1 += __shfl_xor_sync(0xFFFFFFFFu, rs1, 1);
        rs1 += __shfl_xor_sync(0xFFFFFFFFu, rs1, 2);
        l0 = l0 * a0 + rs0;
        l1 = l1 * a1 + rs1;
        #pragma unroll
        for (int j = 0; j < 8; j++) {
            o[j][0] *= a0; o[j][1] *= a0;
            o[j][2] *= a1; o[j][3] *= a1;
        }

        // ---- P -> fp16 A-fragments: 8 k-groups of 16 ----
        uint32_t pf[8][4];
        #pragma unroll
        for (int kk = 0; kk < 8; kk++) {
            pf[kk][0] = pack2h(s[2 * kk][0],     s[2 * kk][1]);
            pf[kk][1] = pack2h(s[2 * kk][2],     s[2 * kk][3]);
            pf[kk][2] = pack2h(s[2 * kk + 1][0], s[2 * kk + 1][1]);
            pf[kk][3] = pack2h(s[2 * kk + 1][2], s[2 * kk + 1][3]);
        }

        // ---- O += P V (V via ldmatrix.trans) ----
        #pragma unroll
        for (int kk = 0; kk < 8; kk++) {
            #pragma unroll
            for (int g = 0; g < 4; g++) {
                uint32_t bf[4];
                ldsm_x4_t(bf, stg + ATILE + (uint32_t)((kk * 16 + vkr) * KVP) + g * 32 + vnc * 16);
                mma_f16(o[g * 2 + 0], pf[kk], bf[0], bf[1]);
                mma_f16(o[g * 2 + 1], pf[kk], bf[2], bf[3]);
            }
        }
        stg_i = (stg_i == 2) ? 0 : stg_i + 1;
        stg_n = (stg_n == 2) ? 0 : stg_n + 1;
    }

    // ---- epilogue ----
    const float inv0 = 1.f / l0, inv1 = 1.f / l1;
    #pragma unroll
    for (int j = 0; j < 8; j++) {
        const int col = j * 8 + 2 * qc;
        *(uint32_t*)(xh + rowbase + (size_t)r0 * DIM + col) = pack2h(o[j][0] * inv0, o[j][1] * inv0);
        *(uint32_t*)(xh + rowbase + (size_t)r1 * DIM + col) = pack2h(o[j][2] * inv1, o[j][3] * inv1);
    }
}

// ---------------- launcher ----------------
extern "C" void kernel_launch(void* const* d_in, const int* in_sizes, int n_in,
                              void* d_out, int out_size) {
    const float* query = (const float*)d_in[0];
    const float* key   = (const float*)d_in[1];
    const float* value = (const float*)d_in[2];
    const float* cond  = (const float*)d_in[3];
    const float* Wq = (const float*)d_in[4];
    const float* bq = (const float*)d_in[5];
    const float* Wk = (const float*)d_in[6];
    const float* bk = (const float*)d_in[7];
    const float* Wv = (const float*)d_in[8];
    const float* bv = (const float*)d_in[9];
    const float* Wo = (const float*)d_in[10];
    const float* bo = (const float*)d_in[11];
    const float* Wc1 = (const float*)d_in[12];
    const float* bc1 = (const float*)d_in[13];
    const float* Wc2 = (const float*)d_in[14];
    float* out = (float*)d_out;

    float *hb, *cb;
    __half *ah3, *wh4, *qkv, *xh;
    cudaGetSymbolAddress((void**)&hb,  g_hb);
    cudaGetSymbolAddress((void**)&cb,  g_cb);
    cudaGetSymbolAddress((void**)&ah3, g_ah3);
    cudaGetSymbolAddress((void**)&wh4, g_wh4);
    cudaGetSymbolAddress((void**)&qkv, g_qkv);
    cudaGetSymbolAddress((void**)&xh,  g_xh);

    cudaFuncSetAttribute(gemm_mma,  cudaFuncAttributeMaxDynamicSharedMemorySize, GEMM_SMEM);
    cudaFuncSetAttribute(flash_mma, cudaFuncAttributeMaxDynamicSharedMemorySize, FA_SMEM);

    const int n4 = MROWS * DIM / 4;

    // cond MLP -> cb
    cond_mlp1<<<dim3(BATCH, HID / 128), 128>>>(cond, Wc1, bc1, hb);
    cond_mlp2<<<dim3(BATCH, DIM / 128), 128>>>(Wc2, cb);

    // all conversions (2 launches)
    conv3<<<dim3(n4 / 256, 3), 256>>>((const float4*)query, (const float4*)key,
                                      (const float4*)value, ah3, n4);
    wT4<<<dim3(DIM / 32, DIM / 32, 4), dim3(32, 8)>>>(Wq, Wk, Wv, Wo, wh4);

    // fused Q/K/V projections (one launch, 768 CTAs)
    gemm_mma<<<dim3(DIM / 128, MROWS / 128, 3), 256, GEMM_SMEM>>>(
        ah3, wh4, bq, bk, bv, cb, nullptr, qkv, SEQ);

    // attention
    flash_mma<<<dim3(SEQ / 128, BATCH * HEADS), 256, FA_SMEM>>>(
        qkv, qkv + (size_t)MROWS * DIM, qkv + 2 * (size_t)MROWS * DIM, xh);

    // output projection -> fp32 out (z=0, W slot 3)
    gemm_mma<<<dim3(DIM / 128, MROWS / 128, 1), 256, GEMM_SMEM>>>(
        xh, wh4 + 3 * (size_t)DIM * DIM, bo, bo, bo, nullptr, out, nullptr, SEQ);
}

// round 17
// speedup vs baseline: 2.2014x; 1.0352x over previous
#include <cuda_runtime.h>
#include <cuda_fp16.h>
#include <cstdint>

// Problem constants
#define BATCH 2
#define SEQ   2048
#define DIM   1024
#define HEADS 16
#define DK    64
#define CL    256
#define HID   512
#define MROWS (BATCH*SEQ)   // 4096

// ---------------- scratch (device globals; no allocation allowed) ----------------
__device__ float g_hb[BATCH * HID];
__device__ float g_cb[BATCH * DIM];
__device__ __half g_ah3[3 * MROWS * DIM];   // fp16 query|key|value inputs
__device__ __half g_wh4[4 * DIM * DIM];     // fp16 W^T for q,k,v,o: [N][K]
__device__ __half g_qkv[3 * MROWS * DIM];   // fp16 q|k|v projected
__device__ __half g_xh[MROWS * DIM];        // fp16 attention output

// ================= PTX helpers (baseline PTX only) =================
__device__ __forceinline__ uint32_t smem_u32(const void* p) {
    uint32_t a;
    asm("{ .reg .u64 t; cvta.to.shared.u64 t, %1; cvt.u32.u64 %0, t; }" : "=r"(a) : "l"(p));
    return a;
}
__device__ __forceinline__ void cp_async16(uint32_t dst, const void* src) {
    asm volatile("cp.async.cg.shared.global [%0], [%1], 16;" :: "r"(dst), "l"(src) : "memory");
}
__device__ __forceinline__ void cp_commit() {
    asm volatile("cp.async.commit_group;" ::: "memory");
}
__device__ __forceinline__ void ldsm_x4(uint32_t* r, uint32_t addr) {
    asm volatile("ldmatrix.sync.aligned.m8n8.x4.shared.b16 {%0,%1,%2,%3}, [%4];"
                 : "=r"(r[0]), "=r"(r[1]), "=r"(r[2]), "=r"(r[3]) : "r"(addr));
}
__device__ __forceinline__ void ldsm_x4_t(uint32_t* r, uint32_t addr) {
    asm volatile("ldmatrix.sync.aligned.m8n8.x4.trans.shared.b16 {%0,%1,%2,%3}, [%4];"
                 : "=r"(r[0]), "=r"(r[1]), "=r"(r[2]), "=r"(r[3]) : "r"(addr));
}
__device__ __forceinline__ void mma_f16(float* d, const uint32_t* a, uint32_t b0, uint32_t b1) {
    asm volatile(
        "mma.sync.aligned.m16n8k16.row.col.f32.f16.f16.f32 "
        "{%0,%1,%2,%3}, {%4,%5,%6,%7}, {%8,%9}, {%0,%1,%2,%3};"
        : "+f"(d[0]), "+f"(d[1]), "+f"(d[2]), "+f"(d[3])
        : "r"(a[0]), "r"(a[1]), "r"(a[2]), "r"(a[3]), "r"(b0), "r"(b1));
}
__device__ __forceinline__ uint32_t pack2h(float lo, float hi) {
    uint32_t r;
    asm("cvt.rn.f16x2.f32 %0, %1, %2;" : "=r"(r) : "f"(hi), "f"(lo));
    return r;
}
__device__ __forceinline__ float ex2(float x) {
    float r; asm("ex2.approx.f32 %0, %1;" : "=f"(r) : "f"(x)); return r;
}
// two fp16 exp2 in one MUFU op
__device__ __forceinline__ uint32_t h2ex2(uint32_t x) {
    uint32_t r; asm("ex2.approx.f16x2 %0, %1;" : "=r"(r) : "r"(x)); return r;
}
#define ONES_H2 0x3C003C00u   // fp16x2 {1.0, 1.0}

// ---------------- conversions (merged, MLP=4) ----------------
// grid (n4/1024, 3); each thread converts 4 strided float4s
__global__ void conv3(const float4* __restrict__ a0, const float4* __restrict__ a1,
                      const float4* __restrict__ a2, __half* __restrict__ o, int n4) {
    int z = blockIdx.y;
    const float4* src = (z == 0) ? a0 : (z == 1) ? a1 : a2;
    __half* dst = o + (size_t)z * MROWS * DIM;
    int base = blockIdx.x * 256 + threadIdx.x;
    const int stride = n4 >> 2;
    #pragma unroll
    for (int k = 0; k < 4; k++) {
        int i = base + k * stride;
        float4 v = src[i];
        ((uint32_t*)dst)[2 * i]     = pack2h(v.x, v.y);
        ((uint32_t*)dst)[2 * i + 1] = pack2h(v.z, v.w);
    }
}

// all four weights W [K,N] -> W^T fp16 [N][K], grid (32,32,4)
__global__ void wT4(const float* __restrict__ w0, const float* __restrict__ w1,
                    const float* __restrict__ w2, const float* __restrict__ w3,
                    __half* __restrict__ oT) {
    __shared__ float t[32][33];
    int z = blockIdx.z;
    const float* W = (z == 0) ? w0 : (z == 1) ? w1 : (z == 2) ? w2 : w3;
    __half* dst = oT + (size_t)z * DIM * DIM;
    int n0 = blockIdx.x * 32, k0 = blockIdx.y * 32;
    int tx = threadIdx.x, ty = threadIdx.y;   // 32 x 8
    #pragma unroll
    for (int i = ty; i < 32; i += 8) t[i][tx] = W[(size_t)(k0 + i) * DIM + n0 + tx];
    __syncthreads();
    #pragma unroll
    for (int i = ty; i < 32; i += 8)
        dst[(size_t)(n0 + i) * DIM + k0 + tx] = __float2half(t[tx][i]);
}

// ---------------- cond MLP (fp32, tiny) ----------------
__global__ void cond_mlp1(const float* __restrict__ cond, const float* __restrict__ Wc1,
                          const float* __restrict__ bc1) {
    int b = blockIdx.x;
    int j = blockIdx.y * 128 + threadIdx.x;
    float acc = bc1[j];
    const float* cr = cond + b * CL;
    #pragma unroll 8
    for (int k = 0; k < CL; k++) acc = fmaf(cr[k], Wc1[k * HID + j], acc);
    g_hb[b * HID + j] = acc > 0.f ? acc : 0.f;
}
__global__ void cond_mlp2(const float* __restrict__ Wc2, float* __restrict__ c) {
    int b = blockIdx.x;
    int n = blockIdx.y * 128 + threadIdx.x;
    float acc = 0.f;
    const float* hr = g_hb + b * HID;
    #pragma unroll 8
    for (int k = 0; k < HID; k++) acc = fmaf(hr[k], Wc2[k * DIM + n], acc);
    c[b * DIM + n] = acc;
}

// ---------------- fp16 mma.sync GEMM (128x128 tile, z-batched) ----------------
#define KC 64
#define NCHUNK (DIM / KC)                // 16
#define TPITCH 144
#define TILE_BYTES (128 * TPITCH)        // 18432
#define STAGE_BYTES (2 * TILE_BYTES)     // 36864
#define GEMM_SMEM (2 * STAGE_BYTES)      // 73728

__device__ __forceinline__ void load_chunk(uint32_t stg, const __half* A, const __half* BT,
                                           int bm, int bn, int k0, int tid) {
    #pragma unroll
    for (int i = 0; i < 8; i++) {
        int idx = tid + i * 256;
        int tile = idx >> 10;                // 0=A, 1=B
        int r = (idx >> 3) & 127;
        int c = (idx & 7) << 4;
        const __half* src = tile ? BT : A;
        int rb = tile ? bn : bm;
        cp_async16(stg + (uint32_t)(tile * TILE_BYTES + r * TPITCH + c),
                   (const char*)(src + (size_t)(rb + r) * DIM + k0) + c);
    }
    cp_commit();
}

__global__ __launch_bounds__(256, 2)
void gemm_mma(const __half* __restrict__ Abase, const __half* __restrict__ Wbase,
              const float* __restrict__ b0, const float* __restrict__ b1,
              const float* __restrict__ b2, const float* __restrict__ cb,
              float* __restrict__ Cf, __half* __restrict__ Chbase, int S) {
    extern __shared__ char smem[];
    uint32_t sbase = smem_u32(smem);
    const int tid = threadIdx.x;
    const int lane = tid & 31, wid = tid >> 5;
    const int wm = wid & 3;
    const int wn = wid >> 2;
    const int bm = blockIdx.y * 128, bn = blockIdx.x * 128;
    const int z = blockIdx.z;

    const __half* A  = Abase + (size_t)z * MROWS * DIM;
    const __half* BT = Wbase + (size_t)z * DIM * DIM;
    const float* bias = (z == 0) ? b0 : (z == 1) ? b1 : b2;
    const float* cbz  = (cb && z == 2) ? cb : nullptr;

    float acc[2][8][4];
    #pragma unroll
    for (int mb = 0; mb < 2; mb++)
        #pragma unroll
        for (int j = 0; j < 8; j++)
            #pragma unroll
            for (int r = 0; r < 4; r++) acc[mb][j][r] = 0.f;

    const int alr = lane & 15, alh = lane >> 4;
    const int bnr = (lane & 7) + (lane >> 4) * 8;
    const int bkh = (lane >> 3) & 1;

    load_chunk(sbase,               A, BT, bm, bn, 0,  tid);
    load_chunk(sbase + STAGE_BYTES, A, BT, bm, bn, KC, tid);

    for (int i = 0; i < NCHUNK; i++) {
        if (i == NCHUNK - 1) asm volatile("cp.async.wait_group 0;" ::: "memory");
        else                 asm volatile("cp.async.wait_group 1;" ::: "memory");
        __syncthreads();

        const uint32_t stg = sbase + (uint32_t)(i & 1) * STAGE_BYTES;
        const uint32_t a_b = stg + wm * 32 * TPITCH;
        const uint32_t b_b = stg + TILE_BYTES + wn * 64 * TPITCH;

        #pragma unroll
        for (int kb = 0; kb < 4; kb++) {
            const uint32_t koff = kb * 32;
            uint32_t ah[2][4];
            #pragma unroll
            for (int mb = 0; mb < 2; mb++)
                ldsm_x4(ah[mb], a_b + (uint32_t)((mb * 16 + alr) * TPITCH) + koff + alh * 16);
            uint32_t bh[4][4];
            #pragma unroll
            for (int g = 0; g < 4; g++)
                ldsm_x4(bh[g], b_b + (uint32_t)((g * 16 + bnr) * TPITCH) + koff + bkh * 16);
            #pragma unroll
            for (int mb = 0; mb < 2; mb++)
                #pragma unroll
                for (int g = 0; g < 4; g++)
                    #pragma unroll
                    for (int h = 0; h < 2; h++)
                        mma_f16(acc[mb][g * 2 + h], ah[mb], bh[g][2 * h], bh[g][2 * h + 1]);
        }
        __syncthreads();
        if (i + 2 < NCHUNK)
            load_chunk(stg, A, BT, bm, bn, (i + 2) * KC, tid);
    }

    const int qr = lane >> 2, qc = lane & 3;
    const int batch = bm / S;
    const float* cbr = cbz ? (cbz + (size_t)batch * DIM) : nullptr;
    __half* Ch = Chbase ? (Chbase + (size_t)z * MROWS * DIM) : nullptr;
    #pragma unroll
    for (int mb = 0; mb < 2; mb++) {
        const int row0 = bm + wm * 32 + mb * 16 + qr;
        #pragma unroll
        for (int j = 0; j < 8; j++) {
            const int col = bn + wn * 64 + j * 8 + qc * 2;
            float b0v = bias[col], b1v = bias[col + 1];
            if (cbr) { b0v += cbr[col]; b1v += cbr[col + 1]; }
            float v0 = acc[mb][j][0] + b0v, v1 = acc[mb][j][1] + b1v;
            float v2 = acc[mb][j][2] + b0v, v3 = acc[mb][j][3] + b1v;
            if (Cf) {
                *(float2*)(Cf + (size_t)row0 * DIM + col)       = make_float2(v0, v1);
                *(float2*)(Cf + (size_t)(row0 + 8) * DIM + col) = make_float2(v2, v3);
            } else {
                *(uint32_t*)(Ch + (size_t)row0 * DIM + col)       = pack2h(v0, v1);
                *(uint32_t*)(Ch + (size_t)(row0 + 8) * DIM + col) = pack2h(v2, v3);
            }
        }
    }
}

// ---------------- flash attention, fp16 mma.sync, Bc=128, f16x2 exp + ones-MMA ----------------
#define ABC 128
#define KVP 144
#define ATILE (ABC * KVP)              // 18432
#define ASTAGE (2 * ATILE)             // 36864
#define FA_SMEM (3 * ASTAGE)           // 110592
#define NKBLK (SEQ / ABC)              // 16

__device__ __forceinline__ void load_kv(uint32_t stg,
        const __half* kh, const __half* vh, size_t rowbase, int kbase, int tid) {
    #pragma unroll
    for (int i = 0; i < 8; i++) {
        int idx = tid + i * 256;
        int t = idx >> 10;                    // 0=K, 1=V
        int r = (idx >> 3) & 127;
        int c = (idx & 7) << 4;
        const __half* src = t ? vh : kh;
        cp_async16(stg + (uint32_t)(t * ATILE + r * KVP + c),
                   (const char*)(src + rowbase + (size_t)(kbase + r) * DIM) + c);
    }
    cp_commit();
}

__global__ __launch_bounds__(256, 1)
void flash_mma(const __half* __restrict__ qh, const __half* __restrict__ kh,
               const __half* __restrict__ vh, __half* __restrict__ xh) {
    extern __shared__ char smem[];
    uint32_t sbase = smem_u32(smem);
    const int tid = threadIdx.x;
    const int lane = tid & 31, w = tid >> 5;
    const int qr = lane >> 2, qc = lane & 3;

    const int qb = blockIdx.x;
    const int bh = blockIdx.y;
    const int b = bh >> 4, h = bh & 15;
    const size_t rowbase = (size_t)b * SEQ * DIM + h * DK;
    const int r0 = qb * 128 + w * 16 + qr;
    const int r1 = r0 + 8;

    const int bnr = (lane & 7) + (lane >> 4) * 8;
    const int bkh = (lane >> 3) & 1;
    const int vkr = (lane & 7) + (((lane >> 3) & 1) << 3);
    const int vnc = lane >> 4;

    uint32_t qf[4][4];
    {
        const __half* qp = qh + rowbase;
        #pragma unroll
        for (int kk = 0; kk < 4; kk++) {
            int c0 = kk * 16 + 2 * qc, c1 = c0 + 8;
            qf[kk][0] = *(const uint32_t*)(qp + (size_t)r0 * DIM + c0);
            qf[kk][1] = *(const uint32_t*)(qp + (size_t)r1 * DIM + c0);
            qf[kk][2] = *(const uint32_t*)(qp + (size_t)r0 * DIM + c1);
            qf[kk][3] = *(const uint32_t*)(qp + (size_t)r1 * DIM + c1);
        }
    }

    load_kv(sbase,          kh, vh, rowbase, 0,   tid);
    load_kv(sbase + ASTAGE, kh, vh, rowbase, ABC, tid);

    float o[8][4];
    #pragma unroll
    for (int j = 0; j < 8; j++)
        #pragma unroll
        for (int r = 0; r < 4; r++) o[j][r] = 0.f;
    float lacc[4] = {0.f, 0.f, 0.f, 0.f};        // row sums via ones-MMA
    float m0 = -1e30f, m1 = -1e30f;
    const float C = 0.125f * 1.4426950408889634f;

    int stg_i = 0, stg_n = 2;
    for (int blk = 0; blk < NKBLK; blk++) {
        __syncthreads();
        if (blk + 2 < NKBLK)
            load_kv(sbase + (uint32_t)stg_n * ASTAGE, kh, vh, rowbase, (blk + 2) * ABC, tid);
        if (blk + 2 < NKBLK)       asm volatile("cp.async.wait_group 2;" ::: "memory");
        else if (blk + 2 == NKBLK) asm volatile("cp.async.wait_group 1;" ::: "memory");
        else                       asm volatile("cp.async.wait_group 0;" ::: "memory");
        __syncthreads();
        const uint32_t stg = sbase + (uint32_t)stg_i * ASTAGE;

        // ---- S = Q K^T ----
        float s[16][4];
        #pragma unroll
        for (int j = 0; j < 16; j++)
            #pragma unroll
            for (int r = 0; r < 4; r++) s[j][r] = 0.f;

        #pragma unroll
        for (int kk = 0; kk < 4; kk++) {
            const uint32_t koff = kk * 32;
            #pragma unroll
            for (int g = 0; g < 8; g++) {
                uint32_t bf[4];
                ldsm_x4(bf, stg + (uint32_t)((g * 16 + bnr) * KVP) + koff + bkh * 16);
                mma_f16(s[g * 2 + 0], qf[kk], bf[0], bf[1]);
                mma_f16(s[g * 2 + 1], qf[kk], bf[2], bf[3]);
            }
        }

        // ---- online max ----
        float mx0 = -1e30f, mx1 = -1e30f;
        #pragma unroll
        for (int j = 0; j < 16; j++) {
            mx0 = fmaxf(mx0, fmaxf(s[j][0], s[j][1]));
            mx1 = fmaxf(mx1, fmaxf(s[j][2], s[j][3]));
        }
        mx0 = fmaxf(mx0, __shfl_xor_sync(0xFFFFFFFFu, mx0, 1));
        mx0 = fmaxf(mx0, __shfl_xor_sync(0xFFFFFFFFu, mx0, 2));
        mx1 = fmaxf(mx1, __shfl_xor_sync(0xFFFFFFFFu, mx1, 1));
        mx1 = fmaxf(mx1, __shfl_xor_sync(0xFFFFFFFFu, mx1, 2));
        float mn0 = fmaxf(m0, mx0), mn1 = fmaxf(m1, mx1);
        float a0 = ex2((m0 - mn0) * C), a1 = ex2((m1 - mn1) * C);
        m0 = mn0; m1 = mn1;

        // rescale O and l accumulators
        #pragma unroll
        for (int j = 0; j < 8; j++) {
            o[j][0] *= a0; o[j][1] *= a0;
            o[j][2] *= a1; o[j][3] *= a1;
        }
        lacc[0] *= a0; lacc[1] *= a0; lacc[2] *= a1; lacc[3] *= a1;

        // ---- exp directly in fp16x2 -> P fragments ----
        uint32_t pf[8][4];
        #pragma unroll
        for (int kk = 0; kk < 8; kk++) {
            const int j0 = 2 * kk, j1 = 2 * kk + 1;
            pf[kk][0] = h2ex2(pack2h((s[j0][0] - m0) * C, (s[j0][1] - m0) * C));
            pf[kk][1] = h2ex2(pack2h((s[j0][2] - m1) * C, (s[j0][3] - m1) * C));
            pf[kk][2] = h2ex2(pack2h((s[j1][0] - m0) * C, (s[j1][1] - m0) * C));
            pf[kk][3] = h2ex2(pack2h((s[j1][2] - m1) * C, (s[j1][3] - m1) * C));
        }

        // ---- row sums: P x ones via MMA (no shfl, fp32 acc) ----
        #pragma unroll
        for (int kk = 0; kk < 8; kk++)
            mma_f16(lacc, pf[kk], ONES_H2, ONES_H2);

        // ---- O += P V (V via ldmatrix.trans) ----
        #pragma unroll
        for (int kk = 0; kk < 8; kk++) {
            #pragma unroll
            for (int g = 0; g < 4; g++) {
                uint32_t bf[4];
                ldsm_x4_t(bf, stg + ATILE + (uint32_t)((kk * 16 + vkr) * KVP) + g * 32 + vnc * 16);
                mma_f16(o[g * 2 + 0], pf[kk], bf[0], bf[1]);
                mma_f16(o[g * 2 + 1], pf[kk], bf[2], bf[3]);
            }
        }
        stg_i = (stg_i == 2) ? 0 : stg_i + 1;
        stg_n = (stg_n == 2) ? 0 : stg_n + 1;
    }

    // ---- epilogue ----
    const float inv0 = 1.f / lacc[0], inv1 = 1.f / lacc[2];
    #pragma unroll
    for (int j = 0; j < 8; j++) {
        const int col = j * 8 + 2 * qc;
        *(uint32_t*)(xh + rowbase + (size_t)r0 * DIM + col) = pack2h(o[j][0] * inv0, o[j][1] * inv0);
        *(uint32_t*)(xh + rowbase + (size_t)r1 * DIM + col) = pack2h(o[j][2] * inv1, o[j][3] * inv1);
    }
}

// ---------------- launcher ----------------
extern "C" void kernel_launch(void* const* d_in, const int* in_sizes, int n_in,
                              void* d_out, int out_size) {
    const float* query = (const float*)d_in[0];
    const float* key   = (const float*)d_in[1];
    const float* value = (const float*)d_in[2];
    const float* cond  = (const float*)d_in[3];
    const float* Wq = (const float*)d_in[4];
    const float* bq = (const float*)d_in[5];
    const float* Wk = (const float*)d_in[6];
    const float* bk = (const float*)d_in[7];
    const float* Wv = (const float*)d_in[8];
    const float* bv = (const float*)d_in[9];
    const float* Wo = (const float*)d_in[10];
    const float* bo = (const float*)d_in[11];
    const float* Wc1 = (const float*)d_in[12];
    const float* bc1 = (const float*)d_in[13];
    const float* Wc2 = (const float*)d_in[14];
    float* out = (float*)d_out;

    float *cb;
    __half *ah3, *wh4, *qkv, *xh;
    cudaGetSymbolAddress((void**)&cb,  g_cb);
    cudaGetSymbolAddress((void**)&ah3, g_ah3);
    cudaGetSymbolAddress((void**)&wh4, g_wh4);
    cudaGetSymbolAddress((void**)&qkv, g_qkv);
    cudaGetSymbolAddress((void**)&xh,  g_xh);

    cudaFuncSetAttribute(gemm_mma,  cudaFuncAttributeMaxDynamicSharedMemorySize, GEMM_SMEM);
    cudaFuncSetAttribute(flash_mma, cudaFuncAttributeMaxDynamicSharedMemorySize, FA_SMEM);

    const int n4 = MROWS * DIM / 4;

    // cond MLP -> cb
    cond_mlp1<<<dim3(BATCH, HID / 128), 128>>>(cond, Wc1, bc1);
    cond_mlp2<<<dim3(BATCH, DIM / 128), 128>>>(Wc2, cb);

    // conversions
    conv3<<<dim3(n4 / 1024, 3), 256>>>((const float4*)query, (const float4*)key,
                                       (const float4*)value, ah3, n4);
    wT4<<<dim3(DIM / 32, DIM / 32, 4), dim3(32, 8)>>>(Wq, Wk, Wv, Wo, wh4);

    // fused Q/K/V projections
    gemm_mma<<<dim3(DIM / 128, MROWS / 128, 3), 256, GEMM_SMEM>>>(
        ah3, wh4, bq, bk, bv, cb, nullptr, qkv, SEQ);

    // attention
    flash_mma<<<dim3(SEQ / 128, BATCH * HEADS), 256, FA_SMEM>>>(
        qkv, qkv + (size_t)MROWS * DIM, qkv + 2 * (size_t)MROWS * DIM, xh);

    // output projection -> fp32 out
    gemm_mma<<<dim3(DIM / 128, MROWS / 128, 1), 256, GEMM_SMEM>>>(
        xh, wh4 + 3 * (size_t)DIM * DIM, bo, bo, bo, nullptr, out, nullptr, SEQ);
}